// round 1
// baseline (speedup 1.0000x reference)
#include <cuda_runtime.h>

#define DD 128
#define HH 160
#define WW 160
#define HWX (HH * WW)          // 25600
#define NV  (DD * HWX)         // 3276800
#define NITER 10

// Gaussian weights: k = exp(-x^2/2), x in [-2,2], normalized.
#define GW0 0.40261995f
#define GW1 0.24420134f
#define GW2 0.05448868f

// Scratch (device globals: allocation-free)
static __device__ float g_warped[NV];
static __device__ float g_vfA[3 * NV];
static __device__ float g_vfB[3 * NV];
static __device__ float g_vfC[3 * NV];

__device__ __forceinline__ float movAt(const float* __restrict__ m, int d, int h, int w) {
    if ((unsigned)d >= DD || (unsigned)h >= HH || (unsigned)w >= WW) return 0.0f;
    return __ldg(m + (d * HH + h) * WW + w);
}

// Pass A: trilinear warp of moving image by vf (mode=constant, cval=0)
__global__ void __launch_bounds__(256) warp_kernel(const float* __restrict__ mov,
                                                   const float* __restrict__ vf,
                                                   float* __restrict__ out) {
    int i = blockIdx.x * 256 + threadIdx.x;
    if (i >= NV) return;
    int w = i % WW;
    int h = (i / WW) % HH;
    int d = i / HWX;

    float cd = (float)d + vf[i];
    float ch = (float)h + vf[NV + i];
    float cw = (float)w + vf[2 * NV + i];

    float fd = floorf(cd), fh = floorf(ch), fw = floorf(cw);
    float td = cd - fd, th = ch - fh, tw = cw - fw;
    int d0 = (int)fd, h0 = (int)fh, w0 = (int)fw;

    float c00 = movAt(mov, d0,     h0,     w0) * (1.0f - tw) + movAt(mov, d0,     h0,     w0 + 1) * tw;
    float c01 = movAt(mov, d0,     h0 + 1, w0) * (1.0f - tw) + movAt(mov, d0,     h0 + 1, w0 + 1) * tw;
    float c10 = movAt(mov, d0 + 1, h0,     w0) * (1.0f - tw) + movAt(mov, d0 + 1, h0,     w0 + 1) * tw;
    float c11 = movAt(mov, d0 + 1, h0 + 1, w0) * (1.0f - tw) + movAt(mov, d0 + 1, h0 + 1, w0 + 1) * tw;

    float c0 = c00 * (1.0f - th) + c01 * th;
    float c1 = c10 * (1.0f - th) + c11 * th;
    out[i] = c0 * (1.0f - td) + c1 * td;
}

// jnp.gradient semantics: central diff interior, one-sided at boundaries
__device__ __forceinline__ float grad_axis(const float* __restrict__ f, int idx,
                                           int pos, int len, int stride) {
    if (pos == 0)        return f[idx + stride] - f[idx];
    if (pos == len - 1)  return f[idx] - f[idx - stride];
    return 0.5f * (f[idx + stride] - f[idx - stride]);
}

// Pass B: demons force + vf update (unsmoothed)
__global__ void __launch_bounds__(256) force_kernel(const float* __restrict__ warped,
                                                    const float* __restrict__ fix,
                                                    const float* __restrict__ vf_in,
                                                    float* __restrict__ vf_out) {
    int i = blockIdx.x * 256 + threadIdx.x;
    if (i >= NV) return;
    int w = i % WW;
    int h = (i / WW) % HH;
    int d = i / HWX;

    float diff = warped[i] - fix[i];

    float g0 = grad_axis(warped, i, d, DD, HWX) + grad_axis(fix, i, d, DD, HWX);
    float g1 = grad_axis(warped, i, h, HH, WW)  + grad_axis(fix, i, h, HH, WW);
    float g2 = grad_axis(warped, i, w, WW, 1)   + grad_axis(fix, i, w, WW, 1);

    float denom = g0 * g0 + g1 * g1 + g2 * g2 + diff * diff;
    float scale = (denom > 1e-6f) ? (-diff / denom) : 0.0f;

    vf_out[i]          = vf_in[i]          + scale * g0;
    vf_out[NV + i]     = vf_in[NV + i]     + scale * g1;
    vf_out[2 * NV + i] = vf_in[2 * NV + i] + scale * g2;
}

// 1D Gaussian smoothing along one axis, zero-padded (SAME).
// pos = (i / STRIDE) % LEN works for all axes since NV is a multiple of each
// axis period, so the channel offset drops out of the modulo.
template <int STRIDE, int LEN>
__global__ void __launch_bounds__(256) smooth_kernel(const float* __restrict__ in,
                                                     float* __restrict__ out) {
    int i = blockIdx.x * 256 + threadIdx.x;
    if (i >= 3 * NV) return;
    int pos = (i / STRIDE) % LEN;

    float acc = GW0 * in[i];
    if (pos >= 1)       acc += GW1 * in[i - STRIDE];
    if (pos >= 2)       acc += GW2 * in[i - 2 * STRIDE];
    if (pos <= LEN - 2) acc += GW1 * in[i + STRIDE];
    if (pos <= LEN - 3) acc += GW2 * in[i + 2 * STRIDE];
    out[i] = acc;
}

extern "C" void kernel_launch(void* const* d_in, const int* in_sizes, int n_in,
                              void* d_out, int out_size) {
    const float* mov = (const float*)d_in[0];
    const float* fix = (const float*)d_in[1];
    float* out = (float*)d_out;

    float *vfA, *vfB, *vfC, *warped;
    cudaGetSymbolAddress((void**)&vfA, g_vfA);
    cudaGetSymbolAddress((void**)&vfB, g_vfB);
    cudaGetSymbolAddress((void**)&vfC, g_vfC);
    cudaGetSymbolAddress((void**)&warped, g_warped);

    cudaMemsetAsync(vfA, 0, sizeof(float) * 3 * NV, 0);

    const int blocksN  = (NV + 255) / 256;
    const int blocks3N = (3 * NV + 255) / 256;

    for (int it = 0; it < NITER; ++it) {
        warp_kernel<<<blocksN, 256>>>(mov, vfA, warped);
        force_kernel<<<blocksN, 256>>>(warped, fix, vfA, vfB);
        // Reference applies conv along D, then H, then W
        smooth_kernel<HWX, DD><<<blocks3N, 256>>>(vfB, vfC);
        smooth_kernel<WW,  HH><<<blocks3N, 256>>>(vfC, vfB);
        float* dst = (it == NITER - 1) ? out : vfA;
        smooth_kernel<1,   WW><<<blocks3N, 256>>>(vfB, dst);
    }
}

// round 2
// speedup vs baseline: 1.8794x; 1.8794x over previous
#include <cuda_runtime.h>

#define DD 128
#define HH 160
#define WW 160
#define W4 40                      // WW / 4
#define HWX (HH * WW)              // 25600
#define HW4 (HH * W4)              // 6400 float4 per slice
#define NV  (DD * HWX)             // 3276800
#define NV4 (DD * HW4)             // 819200 float4 per channel
#define NITER 10

// Gaussian weights: exp(-x^2/2), x in [-2,2], normalized
#define GW0 0.40261995f
#define GW1 0.24420134f
#define GW2 0.05448868f

// Scratch (device globals: allocation-free)
static __device__ float g_sum[NV];     // warped + fixed
static __device__ float g_diff[NV];    // warped - fixed
static __device__ float g_vfA[3 * NV];
static __device__ float g_vfB[3 * NV];
static __device__ float g_vfC[3 * NV];

__device__ __forceinline__ float movAt(const float* __restrict__ m, int d, int h, int w) {
    if ((unsigned)d >= DD || (unsigned)h >= HH || (unsigned)w >= WW) return 0.0f;
    return __ldg(m + (d * HH + h) * WW + w);
}

// ---------------------------------------------------------------------------
// Pass A: trilinear warp; emits sum = warped+fix and diff = warped-fix
// ---------------------------------------------------------------------------
__global__ void __launch_bounds__(256) warp_kernel4(const float* __restrict__ mov,
                                                    const float4* __restrict__ fix,
                                                    const float4* __restrict__ vf,
                                                    float4* __restrict__ sum,
                                                    float4* __restrict__ diff) {
    int i4 = blockIdx.x * 256 + threadIdx.x;
    if (i4 >= NV4) return;
    int w4 = i4 % W4;
    int h  = (i4 / W4) % HH;
    int d  = i4 / HW4;

    float4 v0 = vf[i4], v1 = vf[NV4 + i4], v2 = vf[2 * NV4 + i4];
    float4 fx = fix[i4];
    float4 s, df;

    #pragma unroll
    for (int j = 0; j < 4; ++j) {
        float cd = (float)d        + ((const float*)&v0)[j];
        float ch = (float)h        + ((const float*)&v1)[j];
        float cw = (float)(w4*4+j) + ((const float*)&v2)[j];

        float fd = floorf(cd), fh = floorf(ch), fw = floorf(cw);
        float td = cd - fd, th = ch - fh, tw = cw - fw;
        int d0 = (int)fd, h0 = (int)fh, w0 = (int)fw;

        float c00 = movAt(mov, d0,   h0,   w0) * (1.f-tw) + movAt(mov, d0,   h0,   w0+1) * tw;
        float c01 = movAt(mov, d0,   h0+1, w0) * (1.f-tw) + movAt(mov, d0,   h0+1, w0+1) * tw;
        float c10 = movAt(mov, d0+1, h0,   w0) * (1.f-tw) + movAt(mov, d0+1, h0,   w0+1) * tw;
        float c11 = movAt(mov, d0+1, h0+1, w0) * (1.f-tw) + movAt(mov, d0+1, h0+1, w0+1) * tw;

        float wv = (c00*(1.f-th) + c01*th) * (1.f-td) + (c10*(1.f-th) + c11*th) * td;
        float fv = ((const float*)&fx)[j];
        ((float*)&s)[j]  = wv + fv;
        ((float*)&df)[j] = wv - fv;
    }
    sum[i4]  = s;
    diff[i4] = df;
}

// ---------------------------------------------------------------------------
// Pass B: demons force + vf update.
// grad(warped)+grad(fix) == grad(sum); diff precomputed.
// ---------------------------------------------------------------------------
__global__ void __launch_bounds__(256) force_kernel4(const float4* __restrict__ s,
                                                     const float4* __restrict__ diff,
                                                     const float4* __restrict__ vf_in,
                                                     float4* __restrict__ vf_out) {
    int i4 = blockIdx.x * 256 + threadIdx.x;
    if (i4 >= NV4) return;
    int w4 = i4 % W4;
    int h  = (i4 / W4) % HH;
    int d  = i4 / HW4;

    const float4 z4 = make_float4(0.f, 0.f, 0.f, 0.f);
    float4 sm = s[i4];
    float4 sl = (w4 > 0)      ? s[i4 - 1]   : z4;
    float4 sr = (w4 < W4 - 1) ? s[i4 + 1]   : z4;
    float4 su = (h  > 0)      ? s[i4 - W4]  : z4;   // h-1
    float4 sd = (h  < HH - 1) ? s[i4 + W4]  : z4;   // h+1
    float4 sf = (d  > 0)      ? s[i4 - HW4] : z4;   // d-1
    float4 sb = (d  < DD - 1) ? s[i4 + HW4] : z4;   // d+1
    float4 df4 = diff[i4];

    float4 v0 = vf_in[i4], v1 = vf_in[NV4 + i4], v2 = vf_in[2 * NV4 + i4];
    float4 o0, o1, o2;

    #pragma unroll
    for (int j = 0; j < 4; ++j) {
        int w = w4 * 4 + j;
        float smj = ((const float*)&sm)[j];

        // W-axis gradient (axis 2)
        float left  = (j > 0) ? ((const float*)&sm)[j-1] : sl.w;
        float right = (j < 3) ? ((const float*)&sm)[j+1] : sr.x;
        float g2;
        if (w == 0)            g2 = right - smj;
        else if (w == WW - 1)  g2 = smj - left;
        else                   g2 = 0.5f * (right - left);

        // H-axis gradient (axis 1)
        float up = ((const float*)&su)[j], dn = ((const float*)&sd)[j];
        float g1;
        if (h == 0)            g1 = dn - smj;
        else if (h == HH - 1)  g1 = smj - up;
        else                   g1 = 0.5f * (dn - up);

        // D-axis gradient (axis 0)
        float fr = ((const float*)&sf)[j], bk = ((const float*)&sb)[j];
        float g0;
        if (d == 0)            g0 = bk - smj;
        else if (d == DD - 1)  g0 = smj - fr;
        else                   g0 = 0.5f * (bk - fr);

        float dv = ((const float*)&df4)[j];
        float denom = g0*g0 + g1*g1 + g2*g2 + dv*dv;
        float scale = (denom > 1e-6f) ? (-dv / denom) : 0.0f;

        ((float*)&o0)[j] = ((const float*)&v0)[j] + scale * g0;
        ((float*)&o1)[j] = ((const float*)&v1)[j] + scale * g1;
        ((float*)&o2)[j] = ((const float*)&v2)[j] + scale * g2;
    }
    vf_out[i4]           = o0;
    vf_out[NV4 + i4]     = o1;
    vf_out[2 * NV4 + i4] = o2;
}

// ---------------------------------------------------------------------------
// Fused W+H Gaussian smoothing on one (channel, d, h-tile): smem slice tile.
// Tile: 32 interior H rows + 2 halo each side = 36 rows x 160 W.
// ---------------------------------------------------------------------------
#define TROWS 36
#define IROWS 32
#define NT_HW 5   // 160 / 32

__global__ void __launch_bounds__(256) smoothHW_kernel(const float4* __restrict__ in,
                                                       float4* __restrict__ out) {
    __shared__ float4 s0[TROWS * W4];
    __shared__ float4 s1[TROWS * W4];

    int b  = blockIdx.x;
    int ht = b % NT_HW;
    int d  = (b / NT_HW) % DD;
    int c  = b / (NT_HW * DD);
    int h0 = ht * IROWS;

    const float4* src = in  + (size_t)c * NV4 + (size_t)d * HW4;
    float4*       dst = out + (size_t)c * NV4 + (size_t)d * HW4;
    const float4 z4 = make_float4(0.f, 0.f, 0.f, 0.f);

    // Load 36 rows with H zero-padding
    for (int t = threadIdx.x; t < TROWS * W4; t += 256) {
        int r  = t / W4;
        int cc = t % W4;
        int hg = h0 - 2 + r;
        s0[t] = (hg >= 0 && hg < HH) ? src[hg * W4 + cc] : z4;
    }
    __syncthreads();

    // W-pass (zero-pad SAME): all 36 rows
    for (int t = threadIdx.x; t < TROWS * W4; t += 256) {
        int cc = t % W4;
        float4 m = s0[t];
        float4 l = (cc > 0)      ? s0[t - 1] : z4;
        float4 r = (cc < W4 - 1) ? s0[t + 1] : z4;
        float4 o;
        o.x = GW2*l.z + GW1*l.w + GW0*m.x + GW1*m.y + GW2*m.z;
        o.y = GW2*l.w + GW1*m.x + GW0*m.y + GW1*m.z + GW2*m.w;
        o.z = GW2*m.x + GW1*m.y + GW0*m.z + GW1*m.w + GW2*r.x;
        o.w = GW2*m.y + GW1*m.z + GW0*m.w + GW1*r.x + GW2*r.y;
        s1[t] = o;
    }
    __syncthreads();

    // H-pass over 32 interior rows, write to global
    for (int t = threadIdx.x; t < IROWS * W4; t += 256) {
        int r  = t / W4 + 2;   // local row
        int cc = t % W4;
        float4 a = s1[(r - 2) * W4 + cc];
        float4 b2 = s1[(r - 1) * W4 + cc];
        float4 m = s1[r * W4 + cc];
        float4 e = s1[(r + 1) * W4 + cc];
        float4 f = s1[(r + 2) * W4 + cc];
        float4 o;
        o.x = GW2*(a.x + f.x) + GW1*(b2.x + e.x) + GW0*m.x;
        o.y = GW2*(a.y + f.y) + GW1*(b2.y + e.y) + GW0*m.y;
        o.z = GW2*(a.z + f.z) + GW1*(b2.z + e.z) + GW0*m.z;
        o.w = GW2*(a.w + f.w) + GW1*(b2.w + e.w) + GW0*m.w;
        dst[(h0 + r - 2) * W4 + cc] = o;
    }
}

// ---------------------------------------------------------------------------
// D-axis Gaussian smoothing, float4 vectorized, fully coalesced
// ---------------------------------------------------------------------------
__global__ void __launch_bounds__(256) smoothD_kernel4(const float4* __restrict__ in,
                                                       float4* __restrict__ out) {
    int i4 = blockIdx.x * 256 + threadIdx.x;
    if (i4 >= 3 * NV4) return;
    int d = (i4 / HW4) % DD;   // channel stride NV4 is a multiple of HW4*DD

    float4 m = in[i4];
    float4 acc;
    acc.x = GW0 * m.x; acc.y = GW0 * m.y; acc.z = GW0 * m.z; acc.w = GW0 * m.w;
    if (d >= 1) { float4 a = in[i4 - HW4];
        acc.x += GW1*a.x; acc.y += GW1*a.y; acc.z += GW1*a.z; acc.w += GW1*a.w; }
    if (d >= 2) { float4 a = in[i4 - 2*HW4];
        acc.x += GW2*a.x; acc.y += GW2*a.y; acc.z += GW2*a.z; acc.w += GW2*a.w; }
    if (d <= DD - 2) { float4 a = in[i4 + HW4];
        acc.x += GW1*a.x; acc.y += GW1*a.y; acc.z += GW1*a.z; acc.w += GW1*a.w; }
    if (d <= DD - 3) { float4 a = in[i4 + 2*HW4];
        acc.x += GW2*a.x; acc.y += GW2*a.y; acc.z += GW2*a.z; acc.w += GW2*a.w; }
    out[i4] = acc;
}

extern "C" void kernel_launch(void* const* d_in, const int* in_sizes, int n_in,
                              void* d_out, int out_size) {
    const float* mov = (const float*)d_in[0];
    const float4* fix = (const float4*)d_in[1];
    float4* out4 = (float4*)d_out;

    float *vfA, *vfB, *vfC, *sum, *diff;
    cudaGetSymbolAddress((void**)&vfA, g_vfA);
    cudaGetSymbolAddress((void**)&vfB, g_vfB);
    cudaGetSymbolAddress((void**)&vfC, g_vfC);
    cudaGetSymbolAddress((void**)&sum, g_sum);
    cudaGetSymbolAddress((void**)&diff, g_diff);

    cudaMemsetAsync(vfA, 0, sizeof(float) * 3 * NV, 0);

    const int blocksN4  = NV4 / 256;            // 3200
    const int blocks3N4 = (3 * NV4) / 256;      // 9600
    const int blocksHW  = 3 * DD * NT_HW;       // 1920

    for (int it = 0; it < NITER; ++it) {
        warp_kernel4<<<blocksN4, 256>>>(mov, fix, (const float4*)vfA,
                                        (float4*)sum, (float4*)diff);
        force_kernel4<<<blocksN4, 256>>>((const float4*)sum, (const float4*)diff,
                                         (const float4*)vfA, (float4*)vfB);
        // Separable Gaussian commutes across axes: do (W,H) fused, then D
        smoothHW_kernel<<<blocksHW, 256>>>((const float4*)vfB, (float4*)vfC);
        float4* dst = (it == NITER - 1) ? out4 : (float4*)vfA;
        smoothD_kernel4<<<blocks3N4, 256>>>((const float4*)vfC, dst);
    }
}